// round 12
// baseline (speedup 1.0000x reference)
#include <cuda_runtime.h>
#include <math.h>

// Problem shape (fixed by the dataset)
#define B_DIM 256
#define K_DIM 512
#define D_DIM 1024
#define KPB   128                     // k rows per tile (32 warps x 4 rows)
#define KYN   (K_DIM / KPB)           // 4 tiles per batch row
#define NTILE (B_DIM * KYN)           // 1024 tiles
#define GRID  148                     // 1 block per SM
#define NBIG  136                     // 136*7 + 12*6 = 1024
#define NTHR  1024
#define INV_T 14.2857142857142857f    // 1/0.07

// Scratch (no allocations). Fully overwritten each launch; ticket returns
// to 0 at the end of every launch (graph-replay safe).
__device__ double2      g_part[GRID];
__device__ unsigned int g_ticket;      // zero-initialized at module load

// dynamic smem: q row (4KB) + reductions, padded to ~120KB so exactly ONE
// block is resident per SM (mode-W: no cross-CTA L1tex queue contention).
#define SMEM_BYTES (120 * 1024)
#define OFF_Q     0                    // float q[1024]      (4096 B)
#define OFF_WRED  4096                 // float w_red[64]
#define OFF_SACC  (4096 + 256)         // double sacc[32]
#define OFF_WPOS  (OFF_SACC + 256)     // double w_pos[32]
#define OFF_WFG   (OFF_WPOS + 256)     // double w_fg[32]
#define OFF_FLAG  (OFF_WFG + 256)      // int flag

__global__ __launch_bounds__(NTHR, 1)
void fused_kernel(const float* __restrict__ bg_img,
                  const float* __restrict__ fg_pro,
                  const float* __restrict__ bg_pro,
                  float* __restrict__ out) {
    extern __shared__ unsigned char smem_raw[];
    float*  q_s1  = (float*) (smem_raw + OFF_Q);     // 1024 x float view
    float4* q_s4  = (float4*)(smem_raw + OFF_Q);     // 256 x float4 view
    float*  w_red = (float*) (smem_raw + OFF_WRED);  // 32 ss + 32 fd
    double* sacc  = (double*)(smem_raw + OFF_SACC);
    double* w_pos = (double*)(smem_raw + OFF_WPOS);
    double* w_fg  = (double*)(smem_raw + OFF_WFG);
    int*    s_fl  = (int*)   (smem_raw + OFF_FLAG);

    const int tid  = threadIdx.x;
    const int warp = tid >> 5;        // 0..31
    const int lane = tid & 31;
    const int bid  = blockIdx.x;

    // static contiguous chunk of tiles
    const int lo = (bid < NBIG) ? bid * 7 : NBIG * 7 + (bid - NBIG) * 6;
    const int hi = lo + ((bid < NBIG) ? 7 : 6);

    double acc_lane = 0.0;   // per-lane running sum of exp(bg_logit/T)
    double fg_acc   = 0.0;   // meaningful on tid 0 only
    float  scale    = 0.f;   // inv_norm(b) * INV_T, cached per b
    int    cur_b    = -1;

    for (int t = lo; t < hi; t++) {
        const int b  = t >> 2;          // t / KYN
        const int ky = t & (KYN - 1);   // t % KYN

        if (b != cur_b) {
            // ---- per-b setup: publish RAW q row, reduce sumsq (+fg dot) ----
            __syncthreads();   // previous tile's readers of q_s are done

            const float* qrow = bg_img + (size_t)b * D_DIM;
            float qv = qrow[tid];                 // 1 float per thread
            float ss = qv * qv;

            float fd = 0.f;
            if (ky == 0) {     // this block owns b's fg tile
                fd = qv * fg_pro[(size_t)b * D_DIM + tid];
            }
            #pragma unroll
            for (int o = 16; o; o >>= 1) {
                ss += __shfl_xor_sync(0xFFFFFFFFu, ss, o);
                fd += __shfl_xor_sync(0xFFFFFFFFu, fd, o);
            }
            if (lane == 0) { w_red[warp] = ss; w_red[32 + warp] = fd; }
            q_s1[tid] = qv;                      // raw (unnormalized)
            __syncthreads();                     // q_s + w_red visible

            float tss = 0.f;
            #pragma unroll
            for (int i = 0; i < 32; i++) tss += w_red[i];
            const float inv = 1.0f / sqrtf(tss);
            scale = inv * INV_T;

            if (tid == 0 && ky == 0) {
                float tfd = 0.f;
                #pragma unroll
                for (int i = 0; i < 32; i++) tfd += w_red[32 + i];
                fg_acc += (double)expf(tfd * inv * INV_T);
            }
            cur_b = b;
        }
        // (b unchanged: no sync — loads overlap previous tile's tail)

        // ---- hot loop: warp owns 4 k rows; pure LDG/LDS/FFMA ----
        const int k0 = ky * KPB + warp * 4;
        const float* pbase = bg_pro + ((size_t)b * K_DIM + k0) * D_DIM;
        const float4* p0 = (const float4*)(pbase + (size_t)0 * D_DIM);
        const float4* p1 = (const float4*)(pbase + (size_t)1 * D_DIM);
        const float4* p2 = (const float4*)(pbase + (size_t)2 * D_DIM);
        const float4* p3 = (const float4*)(pbase + (size_t)3 * D_DIM);

        float s0 = 0.f, s1 = 0.f, s2 = 0.f, s3 = 0.f;
        #pragma unroll
        for (int i = 0; i < 8; i++) {
            const int idx = i * 32 + lane;
            float4 qi = q_s4[idx];
            float4 a0 = __ldcs(&p0[idx]);
            float4 a1 = __ldcs(&p1[idx]);
            float4 a2 = __ldcs(&p2[idx]);
            float4 a3 = __ldcs(&p3[idx]);
            s0 = fmaf(qi.x, a0.x, s0); s0 = fmaf(qi.y, a0.y, s0);
            s0 = fmaf(qi.z, a0.z, s0); s0 = fmaf(qi.w, a0.w, s0);
            s1 = fmaf(qi.x, a1.x, s1); s1 = fmaf(qi.y, a1.y, s1);
            s1 = fmaf(qi.z, a1.z, s1); s1 = fmaf(qi.w, a1.w, s1);
            s2 = fmaf(qi.x, a2.x, s2); s2 = fmaf(qi.y, a2.y, s2);
            s2 = fmaf(qi.z, a2.z, s2); s2 = fmaf(qi.w, a2.w, s2);
            s3 = fmaf(qi.x, a3.x, s3); s3 = fmaf(qi.y, a3.y, s3);
            s3 = fmaf(qi.z, a3.z, s3); s3 = fmaf(qi.w, a3.w, s3);
        }

        // ---- tail: 4 shfl trees; inv applied at the exponent ----
        float r;
        r = s0;
        #pragma unroll
        for (int o = 16; o; o >>= 1) r += __shfl_xor_sync(0xFFFFFFFFu, r, o);
        if (lane == 0) acc_lane += (double)expf(r * scale);
        r = s1;
        #pragma unroll
        for (int o = 16; o; o >>= 1) r += __shfl_xor_sync(0xFFFFFFFFu, r, o);
        if (lane == 1) acc_lane += (double)expf(r * scale);
        r = s2;
        #pragma unroll
        for (int o = 16; o; o >>= 1) r += __shfl_xor_sync(0xFFFFFFFFu, r, o);
        if (lane == 2) acc_lane += (double)expf(r * scale);
        r = s3;
        #pragma unroll
        for (int o = 16; o; o >>= 1) r += __shfl_xor_sync(0xFFFFFFFFu, r, o);
        if (lane == 3) acc_lane += (double)expf(r * scale);
    }

    // ---- once-per-block reduction + ticketed finish ----
    #pragma unroll
    for (int o = 16; o; o >>= 1)
        acc_lane += __shfl_xor_sync(0xFFFFFFFFu, acc_lane, o);
    __syncthreads();
    if (lane == 0) sacc[warp] = acc_lane;
    __syncthreads();

    if (tid == 0) {
        double tsum = 0.0;
        #pragma unroll
        for (int i = 0; i < 32; i++) tsum += sacc[i];
        g_part[bid] = make_double2(tsum, fg_acc);
        __threadfence();
        unsigned int done = atomicAdd(&g_ticket, 1u);
        *s_fl = (done == (unsigned int)(GRID - 1)) ? 1 : 0;
    }
    __syncthreads();

    if (*s_fl) {
        const volatile double* vp = reinterpret_cast<const volatile double*>(g_part);
        double pos = 0.0, fg = 0.0;
        for (int i = tid; i < GRID; i += NTHR) {
            pos += vp[2 * i + 0];
            fg  += vp[2 * i + 1];
        }
        #pragma unroll
        for (int o = 16; o; o >>= 1) {
            pos += __shfl_xor_sync(0xFFFFFFFFu, pos, o);
            fg  += __shfl_xor_sync(0xFFFFFFFFu, fg,  o);
        }
        if (lane == 0) { w_pos[warp] = pos; w_fg[warp] = fg; }
        __syncthreads();
        if (tid == 0) {
            double P = 0.0, F = 0.0;
            #pragma unroll
            for (int i = 0; i < 32; i++) { P += w_pos[i]; F += w_fg[i]; }
            // -log(pos/neg) = log1p(K * F / S)
            out[0] = (float)log1p(F * (double)K_DIM / P);
            g_ticket = 0;   // restore for next graph replay
        }
    }
}

extern "C" void kernel_launch(void* const* d_in, const int* in_sizes, int n_in,
                              void* d_out, int out_size) {
    const float* bg_img = (const float*)d_in[0];   // [B, D]
    const float* fg_pro = (const float*)d_in[1];   // [B, D]
    const float* bg_pro = (const float*)d_in[2];   // [B, K, D]
    float* out = (float*)d_out;

    cudaFuncSetAttribute(fused_kernel,
                         cudaFuncAttributeMaxDynamicSharedMemorySize, SMEM_BYTES);
    fused_kernel<<<GRID, NTHR, SMEM_BYTES>>>(bg_img, fg_pro, bg_pro, out);
}

// round 13
// speedup vs baseline: 1.0410x; 1.0410x over previous
#include <cuda_runtime.h>
#include <math.h>

// Problem shape (fixed by the dataset)
#define B_DIM 256
#define K_DIM 512
#define D_DIM 1024
#define KPB   64                      // k rows per tile (16 warps x 4 rows)
#define KYN   (K_DIM / KPB)           // 8 tiles per batch row
#define NTILE (B_DIM * KYN)           // 2048 tiles
#define GRID  296                     // 148 SMs x 2 resident blocks
#define NSTAT 6                       // static tiles per block (296*6 = 1776)
#define POOL0 (GRID * NSTAT)          // 1776 = start of dynamic pool (b=222 edge)
#define NTHR  512
#define INV_T 14.2857142857142857f    // 1/0.07

// Scratch (no allocations). Fully overwritten each launch; both counters
// return to 0 at the end of every launch (graph-replay safe).
__device__ double2      g_part[GRID];
__device__ unsigned int g_ticket;      // completion ticket (zero-init)
__device__ unsigned int g_work;        // steal-pool counter (zero-init)

// dynamic smem: q row (4KB) + reductions, padded to 80KB so exactly TWO
// blocks are resident per SM (measured optimum for L1tex-queue contention).
#define SMEM_BYTES (80 * 1024)
#define OFF_Q     0                    // float q[1024]      (4096 B)
#define OFF_WRED  4096                 // float w_red[32]
#define OFF_SACC  (4096 + 128)         // double sacc[16]
#define OFF_WPOS  (OFF_SACC + 128)     // double w_pos[16]
#define OFF_WFG   (OFF_WPOS + 128)     // double w_fg[16]
#define OFF_TILE  (OFF_WFG + 128)      // int s_t
#define OFF_FLAG  (OFF_TILE + 64)      // int flag

__global__ __launch_bounds__(NTHR, 2)
void fused_kernel(const float* __restrict__ bg_img,
                  const float* __restrict__ fg_pro,
                  const float* __restrict__ bg_pro,
                  float* __restrict__ out) {
    extern __shared__ unsigned char smem_raw[];
    float2* q_s2  = (float2*)(smem_raw + OFF_Q);
    float4* q_s4  = (float4*)(smem_raw + OFF_Q);
    float*  w_red = (float*) (smem_raw + OFF_WRED);  // 16 ss + 16 fd
    double* sacc  = (double*)(smem_raw + OFF_SACC);
    double* w_pos = (double*)(smem_raw + OFF_WPOS);
    double* w_fg  = (double*)(smem_raw + OFF_WFG);
    int*    s_t   = (int*)   (smem_raw + OFF_TILE);
    int*    s_fl  = (int*)   (smem_raw + OFF_FLAG);

    const int tid  = threadIdx.x;
    const int warp = tid >> 5;        // 0..15
    const int lane = tid & 31;
    const int bid  = blockIdx.x;

    double acc_lane = 0.0;   // per-lane running sum of exp(bg_logit/T)
    double fg_acc   = 0.0;   // meaningful on tid 0 only
    float  scale    = 0.f;   // inv_norm(b) * INV_T, cached per b
    int    cur_b    = -1;

    // process one tile t (b-setup on change, then stream KPB rows)
    auto process = [&](int t) {
        const int b  = t >> 3;          // t / KYN
        const int ky = t & (KYN - 1);   // t % KYN

        if (b != cur_b) {
            __syncthreads();   // previous tile's readers of q_s are done

            const float2* qrow = (const float2*)(bg_img + (size_t)b * D_DIM);
            float2 qv = qrow[tid];
            float ss = qv.x*qv.x + qv.y*qv.y;

            float fd = 0.f;
            if (ky == 0) {     // ascending dispensing => fg seen exactly once
                const float2* frow = (const float2*)(fg_pro + (size_t)b * D_DIM);
                float2 f = frow[tid];
                fd = qv.x*f.x + qv.y*f.y;
            }
            #pragma unroll
            for (int o = 16; o; o >>= 1) {
                ss += __shfl_xor_sync(0xFFFFFFFFu, ss, o);
                fd += __shfl_xor_sync(0xFFFFFFFFu, fd, o);
            }
            if (lane == 0) { w_red[warp] = ss; w_red[16 + warp] = fd; }
            q_s2[tid] = qv;                      // raw (unnormalized)
            __syncthreads();                     // q_s + w_red visible

            float tss = 0.f;
            #pragma unroll
            for (int i = 0; i < 16; i++) tss += w_red[i];
            const float inv = 1.0f / sqrtf(tss);
            scale = inv * INV_T;

            if (tid == 0 && ky == 0) {
                float tfd = 0.f;
                #pragma unroll
                for (int i = 0; i < 16; i++) tfd += w_red[16 + i];
                fg_acc += (double)expf(tfd * inv * INV_T);
            }
            cur_b = b;
        }

        // ---- hot loop: warp owns 4 k rows; pure LDG/LDS/FFMA ----
        const int k0 = ky * KPB + warp * 4;
        const float* pbase = bg_pro + ((size_t)b * K_DIM + k0) * D_DIM;
        const float4* p0 = (const float4*)(pbase + (size_t)0 * D_DIM);
        const float4* p1 = (const float4*)(pbase + (size_t)1 * D_DIM);
        const float4* p2 = (const float4*)(pbase + (size_t)2 * D_DIM);
        const float4* p3 = (const float4*)(pbase + (size_t)3 * D_DIM);

        float s0 = 0.f, s1 = 0.f, s2 = 0.f, s3 = 0.f;
        #pragma unroll
        for (int i = 0; i < 8; i++) {
            const int idx = i * 32 + lane;
            float4 qi = q_s4[idx];
            float4 a0 = __ldcs(&p0[idx]);
            float4 a1 = __ldcs(&p1[idx]);
            float4 a2 = __ldcs(&p2[idx]);
            float4 a3 = __ldcs(&p3[idx]);
            s0 = fmaf(qi.x, a0.x, s0); s0 = fmaf(qi.y, a0.y, s0);
            s0 = fmaf(qi.z, a0.z, s0); s0 = fmaf(qi.w, a0.w, s0);
            s1 = fmaf(qi.x, a1.x, s1); s1 = fmaf(qi.y, a1.y, s1);
            s1 = fmaf(qi.z, a1.z, s1); s1 = fmaf(qi.w, a1.w, s1);
            s2 = fmaf(qi.x, a2.x, s2); s2 = fmaf(qi.y, a2.y, s2);
            s2 = fmaf(qi.z, a2.z, s2); s2 = fmaf(qi.w, a2.w, s2);
            s3 = fmaf(qi.x, a3.x, s3); s3 = fmaf(qi.y, a3.y, s3);
            s3 = fmaf(qi.z, a3.z, s3); s3 = fmaf(qi.w, a3.w, s3);
        }

        // ---- tail: 4 shfl trees; inv applied at the exponent ----
        float r;
        r = s0;
        #pragma unroll
        for (int o = 16; o; o >>= 1) r += __shfl_xor_sync(0xFFFFFFFFu, r, o);
        if (lane == 0) acc_lane += (double)expf(r * scale);
        r = s1;
        #pragma unroll
        for (int o = 16; o; o >>= 1) r += __shfl_xor_sync(0xFFFFFFFFu, r, o);
        if (lane == 1) acc_lane += (double)expf(r * scale);
        r = s2;
        #pragma unroll
        for (int o = 16; o; o >>= 1) r += __shfl_xor_sync(0xFFFFFFFFu, r, o);
        if (lane == 2) acc_lane += (double)expf(r * scale);
        r = s3;
        #pragma unroll
        for (int o = 16; o; o >>= 1) r += __shfl_xor_sync(0xFFFFFFFFu, r, o);
        if (lane == 3) acc_lane += (double)expf(r * scale);
    };

    // ---- phase 1: static contiguous chunk of NSTAT tiles ----
    #pragma unroll 1
    for (int i = 0; i < NSTAT; i++)
        process(bid * NSTAT + i);

    // ---- phase 2: steal from the tail pool (272 tiles) ----
    for (;;) {
        if (tid == 0) *s_t = (int)(POOL0 + atomicAdd(&g_work, 1u));
        __syncthreads();               // broadcast; also fences q_s reuse
        const int t = *s_t;
        if (t >= NTILE) break;
        process(t);
    }

    // ---- once-per-block reduction + ticketed finish ----
    #pragma unroll
    for (int o = 16; o; o >>= 1)
        acc_lane += __shfl_xor_sync(0xFFFFFFFFu, acc_lane, o);
    __syncthreads();
    if (lane == 0) sacc[warp] = acc_lane;
    __syncthreads();

    if (tid == 0) {
        double tsum = 0.0;
        #pragma unroll
        for (int i = 0; i < 16; i++) tsum += sacc[i];
        g_part[bid] = make_double2(tsum, fg_acc);
        __threadfence();
        unsigned int done = atomicAdd(&g_ticket, 1u);
        *s_fl = (done == (unsigned int)(GRID - 1)) ? 1 : 0;
    }
    __syncthreads();

    if (*s_fl) {
        const volatile double* vp = reinterpret_cast<const volatile double*>(g_part);
        double pos = 0.0, fg = 0.0;
        for (int i = tid; i < GRID; i += NTHR) {
            pos += vp[2 * i + 0];
            fg  += vp[2 * i + 1];
        }
        #pragma unroll
        for (int o = 16; o; o >>= 1) {
            pos += __shfl_xor_sync(0xFFFFFFFFu, pos, o);
            fg  += __shfl_xor_sync(0xFFFFFFFFu, fg,  o);
        }
        if (lane == 0) { w_pos[warp] = pos; w_fg[warp] = fg; }
        __syncthreads();
        if (tid == 0) {
            double P = 0.0, F = 0.0;
            #pragma unroll
            for (int i = 0; i < 16; i++) { P += w_pos[i]; F += w_fg[i]; }
            // -log(pos/neg) = log1p(K * F / S)
            out[0] = (float)log1p(F * (double)K_DIM / P);
            g_work   = 0;   // restore for next graph replay
            g_ticket = 0;
        }
    }
}

extern "C" void kernel_launch(void* const* d_in, const int* in_sizes, int n_in,
                              void* d_out, int out_size) {
    const float* bg_img = (const float*)d_in[0];   // [B, D]
    const float* fg_pro = (const float*)d_in[1];   // [B, D]
    const float* bg_pro = (const float*)d_in[2];   // [B, K, D]
    float* out = (float*)d_out;

    cudaFuncSetAttribute(fused_kernel,
                         cudaFuncAttributeMaxDynamicSharedMemorySize, SMEM_BYTES);
    fused_kernel<<<GRID, NTHR, SMEM_BYTES>>>(bg_img, fg_pro, bg_pro, out);
}